// round 9
// baseline (speedup 1.0000x reference)
#include <cuda_runtime.h>
#include <cuda_bf16.h>

#define D 128
#define B_MAX 16384
#define CHUNK 128          // rows per warp

// Boundary-segment accumulators + flags. Zero at load; every launch restores
// zero (finalize re-zeroes exactly what was touched).
__device__ float g_num[B_MAX * D];   // 8 MB
__device__ float g_esum[B_MAX];
__device__ int   g_flag[B_MAX];      // 0=untouched, 1=boundary(atomic), 2=interior(done)

__device__ __forceinline__ float fast_tanh(float v) {
    float r;
    asm("tanh.approx.f32 %0, %1;" : "=f"(r) : "f"(v));
    return r;
}

// Streaming (evict-first) float4 load: data touched exactly once.
__device__ __forceinline__ float4 ldcs_f4(const float* p) {
    float4 v;
    asm("ld.global.cs.v4.f32 {%0,%1,%2,%3}, [%4];"
        : "=f"(v.x), "=f"(v.y), "=f"(v.z), "=f"(v.w) : "l"(p));
    return v;
}

__global__ __launch_bounds__(256) void logits_accum_kernel(
    const float* __restrict__ x,
    const float* __restrict__ refm,
    const int*   __restrict__ index,
    const float* __restrict__ W,
    const float* __restrict__ bptr,
    float*       __restrict__ out,
    int n)
{
    const int tid  = threadIdx.x;
    const int w    = tid >> 5;
    const int lane = tid & 31;
    const unsigned FULL = 0xffffffffu;

    __shared__ int s_idx[8][CHUNK];   // 4 KB: segment ids for each warp's rows

    const int chunk = (blockIdx.x * 8 + w) * CHUNK;
    if (chunk >= n) return;
    const bool full = (chunk + CHUNK) <= n;

    // Stage this warp's 128 segment ids into smem (clamped).
    #pragma unroll
    for (int j = 0; j < 4; j++) {
        const int ri = chunk + j * 32 + lane;
        s_idx[w][j * 32 + lane] = index[ri < n ? ri : (n - 1)];
    }
    __syncwarp();

    const int leftprev  = (chunk == 0) ? -1 : index[chunk - 1];
    const int rightnext = (chunk + CHUNK >= n) ? -1 : index[chunk + CHUNK];

    // W in registers: lane owns feature columns [4*lane, 4*lane+3]
    const float4 Wa = ((const float4*)W)[lane];
    const float4 Wb = ((const float4*)W)[32 + lane];
    const float  bb = bptr[0];

    const float* xlane = x    + (size_t)lane * 4;
    const float* rlane = refm + (size_t)lane * 4;

    int    cur  = s_idx[w][0];
    float4 acc  = make_float4(0.f, 0.f, 0.f, 0.f);
    float  esum = 0.f;   // identical in all lanes (e[k] is warp-uniform)

    // Flush segment `cur`. Interior (fully inside this chunk) -> direct out
    // write, no atomics. Boundary -> atomic accumulate + flag for finalize.
    auto flush = [&](int seg, bool right_complete) {
        const bool interior = right_complete && (seg != leftprev);
        if (interior) {
            const float inv = 1.0f / (esum + 1e-16f);
            ((float4*)(out + (size_t)seg * D))[lane] =
                make_float4(acc.x * inv, acc.y * inv, acc.z * inv, acc.w * inv);
            if (lane == 0) g_flag[seg] = 2;
        } else {
            float* dst = g_num + (size_t)seg * D + lane * 4;
            atomicAdd(dst + 0, acc.x);
            atomicAdd(dst + 1, acc.y);
            atomicAdd(dst + 2, acc.z);
            atomicAdd(dst + 3, acc.w);
            if (lane == 0) {
                atomicAdd(&g_esum[seg], esum);
                g_flag[seg] = 1;      // racers write the same value
            }
        }
    };

    #pragma unroll 4
    for (int g = 0; g < CHUNK / 4; g++) {
        const int r0 = chunk + 4 * g;
        if (!full && r0 >= n) break;

        float4 xv[4];
        float  p[4];
        #pragma unroll
        for (int k = 0; k < 4; k++) {
            const int r = r0 + k;
            if (full || r < n) {
                xv[k]           = ldcs_f4(xlane + (size_t)r * D);
                const float4 rv = ldcs_f4(rlane + (size_t)r * D);
                p[k] = xv[k].x * Wa.x + xv[k].y * Wa.y + xv[k].z * Wa.z + xv[k].w * Wa.w
                     + rv.x    * Wb.x + rv.y    * Wb.y + rv.z    * Wb.z + rv.w    * Wb.w;
            } else {
                xv[k] = make_float4(0.f, 0.f, 0.f, 0.f);
                p[k]  = 0.f;
            }
        }

        // Tree-merge 4-row reduction: 9 shuffles.
        float t0 = __shfl_xor_sync(FULL, p[0], 16);
        float t1 = __shfl_xor_sync(FULL, p[1], 16);
        float q0 = (lane & 16) ? (p[1] + t1) : (p[0] + t0);
        float t2 = __shfl_xor_sync(FULL, p[2], 16);
        float t3 = __shfl_xor_sync(FULL, p[3], 16);
        float q1 = (lane & 16) ? (p[3] + t3) : (p[2] + t2);
        float u0 = __shfl_xor_sync(FULL, q0, 8);
        float u1 = __shfl_xor_sync(FULL, q1, 8);
        float v  = (lane & 8) ? (q1 + u1) : (q0 + u0);
        v += __shfl_xor_sync(FULL, v, 4);
        v += __shfl_xor_sync(FULL, v, 2);
        v += __shfl_xor_sync(FULL, v, 1);
        // Row sums: lane 0 -> row0, 16 -> row1, 8 -> row2, 24 -> row3.

        // softmax shift-invariant + tanh bounded: no segment max needed.
        const float ev = __expf(fast_tanh(v + bb));
        float e[4];
        e[0] = __shfl_sync(FULL, ev, 0);
        e[1] = __shfl_sync(FULL, ev, 16);
        e[2] = __shfl_sync(FULL, ev, 8);
        e[3] = __shfl_sync(FULL, ev, 24);

        #pragma unroll
        for (int k = 0; k < 4; k++) {
            const int r = r0 + k;
            if (!full && r >= n) break;              // warp-uniform
            const int sk = s_idx[w][4 * g + k];      // LDS broadcast
            if (sk != cur) {                         // segment ended inside chunk
                flush(cur, true);
                acc = make_float4(0.f, 0.f, 0.f, 0.f);
                esum = 0.f;
                cur = sk;
            }
            acc.x += e[k] * xv[k].x;
            acc.y += e[k] * xv[k].y;
            acc.z += e[k] * xv[k].z;
            acc.w += e[k] * xv[k].w;
            esum  += e[k];
        }
    }

    // Final flush: right-complete iff the next chunk starts a new segment.
    flush(cur, rightnext != cur);
}

#define SEGS_PER_WARP 4

// Finalize: only boundary segments (flag==1) need the divide; untouched
// segments (flag==0) get zeros; interior (flag==2) already written. All
// flags reset to 0; g_num/g_esum re-zeroed where touched.
__global__ __launch_bounds__(256) void finalize_kernel(float* __restrict__ out)
{
    const int warp0 = ((blockIdx.x * blockDim.x + threadIdx.x) >> 5) * SEGS_PER_WARP;
    const int lane  = threadIdx.x & 31;
    const unsigned FULL = 0xffffffffu;

    const int myflag = (lane < SEGS_PER_WARP) ? g_flag[warp0 + lane] : 0;

    #pragma unroll
    for (int i = 0; i < SEGS_PER_WARP; i++) {
        const int f = __shfl_sync(FULL, myflag, i);
        const int s = warp0 + i;
        if (f == 1) {
            float4* numv = (float4*)(g_num + (size_t)s * D);
            const float4 v  = numv[lane];
            const float  es = g_esum[s];
            const float  inv = 1.0f / (es + 1e-16f);
            ((float4*)(out + (size_t)s * D))[lane] =
                make_float4(v.x * inv, v.y * inv, v.z * inv, v.w * inv);
            numv[lane] = make_float4(0.f, 0.f, 0.f, 0.f);
            if (lane == 0) g_esum[s] = 0.f;
        } else if (f == 0) {
            ((float4*)(out + (size_t)s * D))[lane] = make_float4(0.f, 0.f, 0.f, 0.f);
        }
        // f == 2: interior, already written by the main kernel.
    }
    __syncwarp();
    if (lane < SEGS_PER_WARP) g_flag[warp0 + lane] = 0;
}

extern "C" void kernel_launch(void* const* d_in, const int* in_sizes, int n_in,
                              void* d_out, int out_size) {
    // metadata order: x, ref, index, batch_size, W, b
    const float* x     = (const float*)d_in[0];
    const float* refm  = (const float*)d_in[1];
    const int*   index = (const int*)  d_in[2];
    const float* W     = (const float*)d_in[4];
    const float* b     = (const float*)d_in[5];
    float* out = (float*)d_out;

    const int n = in_sizes[0] / D;   // 500000
    const int B = out_size / D;      // 16384

    const int rows_per_cta = 8 * CHUNK;                      // 1024
    const int grid = (n + rows_per_cta - 1) / rows_per_cta;  // 489

    logits_accum_kernel<<<grid, 256>>>(x, refm, index, W, b, out, n);
    finalize_kernel<<<B / (8 * SEGS_PER_WARP), 256>>>(out);  // 512 CTAs
}